// round 10
// baseline (speedup 1.0000x reference)
#include <cuda_runtime.h>
#include <math.h>

#define NUM_CLASSES 40
#define N_GT 20
#define MAX_B 8
#define MAX_T 16
#define MAX_BT (MAX_B * MAX_T)
#define MAX_P 25600
#define INNER_TH 0.5f
#define SUPPRESS_V 1e9f

// Sorted (by mean area, ascending, stable) per-instance data.
// g_box: cx, cy, wclip(=max(w,0.05)), hclip
__device__ float4 g_box[MAX_B][N_GT][MAX_T];
__device__ int    g_lab[MAX_B][N_GT];
__device__ int    g_id [MAX_B][N_GT][MAX_T];
__device__ int    g_valid[MAX_B][N_GT];
// Per-point claim key: (claimer_n << 32) | f32bits(d).  ~0 = unclaimed.
__device__ unsigned long long g_key[MAX_BT * MAX_P];

// ---------------------------------------------------------------------------
// Init claim keys
// ---------------------------------------------------------------------------
__global__ void init_kernel(int total)
{
    int i = blockIdx.x * blockDim.x + threadIdx.x;
    if (i < total) g_key[i] = ~0ull;
}

// ---------------------------------------------------------------------------
// Prep: area -> stable argsort per batch -> gather sorted params
// ---------------------------------------------------------------------------
__global__ void prep_kernel(const int* __restrict__ labels,
                            const float* __restrict__ boxes,
                            const int* __restrict__ ids,
                            int B, int T)
{
    __shared__ float s_area[MAX_B][N_GT];
    __shared__ int   s_order[MAX_B][N_GT];
    int tid = threadIdx.x;
    int total = B * N_GT;

    if (tid < total) {
        int b = tid / N_GT, n = tid % N_GT;
        float sum = 0.0f;
        for (int t = 0; t < T; t++) {
            const float* bx = boxes + (((size_t)(b * N_GT + n) * T + t) * 4);
            float w = bx[2] - bx[0];
            float h = bx[3] - bx[1];
            sum += w * h;
        }
        s_area[b][n] = sum / (float)T;
    }
    __syncthreads();

    if (tid < B) {
        int b = tid;
        int ord[N_GT];
        for (int i = 0; i < N_GT; i++) ord[i] = i;
        for (int i = 1; i < N_GT; i++) {          // stable insertion sort
            int key = ord[i];
            float ka = s_area[b][key];
            int j = i - 1;
            while (j >= 0 && s_area[b][ord[j]] > ka) { ord[j + 1] = ord[j]; j--; }
            ord[j + 1] = key;
        }
        for (int i = 0; i < N_GT; i++) s_order[b][i] = ord[i];
    }
    __syncthreads();

    if (tid < total) {
        int b = tid / N_GT, n = tid % N_GT;
        int src = s_order[b][n];
        int lab = labels[b * N_GT + src];
        g_lab[b][n] = lab;
        int anyv = 0;
        for (int t = 0; t < T; t++) {
            const float* bx = boxes + (((size_t)(b * N_GT + src) * T + t) * 4);
            float x1 = bx[0], y1 = bx[1], x2 = bx[2], y2 = bx[3];
            float w = x2 - x1, h = y2 - y1;
            anyv |= (w > 0.0f && h > 0.0f) ? 1 : 0;
            float4 v;
            v.x = (x1 + x2) * 0.5f;
            v.y = (y1 + y2) * 0.5f;
            v.z = fmaxf(w, 0.05f);
            v.w = fmaxf(h, 0.05f);
            g_box[b][n][t] = v;
            g_id[b][n][t] = ids[(size_t)(b * N_GT + src) * T + t];
        }
        g_valid[b][n] = (anyv && lab >= 0) ? 1 : 0;
    }
}

// ---------------------------------------------------------------------------
// Phase 1: one block per (b,t,n). atomicMin packed (n, d) for every point
// inside the instance's d<0.5 ellipse (bbox-culled). Fully parallel.
// ---------------------------------------------------------------------------
__global__ void __launch_bounds__(256)
phase1_kernel(const float* __restrict__ ref, int T, int P, int W)
{
    int inst = blockIdx.x;                 // bt * N_GT + n
    int bt = inst / N_GT, n = inst % N_GT;
    int b = bt / T, t = bt % T;

    if (!g_valid[b][n]) return;
    int gid = g_id[b][n][t];
    if (gid == -1) return;

    float4 v = g_box[b][n][t];
    float cx = v.x, cy = v.y, wc = v.z, hc = v.w;
    float iw = 1.0f / wc, ih = 1.0f / hc;

    int ix0 = 0, iy0 = 0, bw = 0, cnt = P;
    if (W > 0) {
        int H = P / W;
        float Wf = (float)W, Hf = (float)H;
        float rx = wc * 0.7072f;
        float ry = hc * 0.7072f;
        ix0 = max(0,     (int)floorf((cx - rx) * Wf - 0.5f) - 2);
        int ix1 = min(W - 1, (int)ceilf((cx + rx) * Wf - 0.5f) + 2);
        iy0 = max(0,     (int)floorf((cy - ry) * Hf - 0.5f) - 2);
        int iy1 = min(H - 1, (int)ceilf((cy + ry) * Hf - 0.5f) + 2);
        bw = ix1 - ix0 + 1;
        cnt = (ix1 >= ix0 && iy1 >= iy0) ? bw * (iy1 - iy0 + 1) : 0;
    }

    const float2* rp2 = (const float2*)ref;
    unsigned long long base = (unsigned long long)(unsigned)n << 32;
    unsigned long long* keys = g_key + (size_t)bt * P;

    for (int idx = threadIdx.x; idx < cnt; idx += 256) {
        int p = (W > 0) ? ((iy0 + idx / bw) * W + (ix0 + idx % bw)) : idx;
        float2 r = rp2[p];
        float dx = (cx - r.x) * iw;
        float dy = (cy - r.y) * ih;
        float d = dx * dx + dy * dy;
        if (fabsf(d - INNER_TH) < 1e-5f) {
            // boundary band: redo with exact division (reference semantics)
            float ex = (cx - r.x) / wc;
            float ey = (cy - r.y) / hc;
            d = ex * ex + ey * ey;
        }
        if (d < INNER_TH)
            atomicMin(&keys[p], base | (unsigned long long)__float_as_uint(d));
    }
}

// ---------------------------------------------------------------------------
// Phase 2: one block per (b,t). Resolve rare fallback claims exactly.
// ---------------------------------------------------------------------------
__global__ void __launch_bounds__(1024)
phase2_kernel(const float* __restrict__ ref, int T, int P)
{
    int bt = blockIdx.x;
    int b = bt / T, t = bt % T;
    int tid = threadIdx.x;
    int lane = tid & 31, warp = tid >> 5;

    __shared__ unsigned char s_n[MAX_P];     // current claimer per point (255 = none)
    __shared__ int   s_cnt[N_GT];
    __shared__ int   s_act[N_GT];
    __shared__ float s_cx[N_GT], s_cy[N_GT], s_wc[N_GT], s_hc[N_GT];
    __shared__ float s_rd[32];
    __shared__ int   s_ri[32];
    __shared__ float s_gd;
    __shared__ int   s_gi;

    if (tid < N_GT) {
        float4 v = g_box[b][tid][t];
        s_cx[tid] = v.x; s_cy[tid] = v.y; s_wc[tid] = v.z; s_hc[tid] = v.w;
        int id = g_id[b][tid][t];
        s_act[tid] = (g_valid[b][tid] && id != -1) ? 1 : 0;
        s_cnt[tid] = 0;
    }
    __syncthreads();

    unsigned long long* keys = g_key + (size_t)bt * P;
    for (int p = tid; p < P; p += 1024) {
        unsigned long long k = keys[p];
        unsigned n = (unsigned)(k >> 32);
        unsigned char nn = (n < N_GT) ? (unsigned char)n : (unsigned char)255;
        s_n[p] = nn;
        if (nn < N_GT) atomicAdd(&s_cnt[nn], 1);
    }
    __syncthreads();

    const float2* rp2 = (const float2*)ref;

    for (int n = 0; n < N_GT; n++) {
        bool fb = s_act[n] && (s_cnt[n] == 0);   // uniform across block
        if (!fb) continue;

        float cx = s_cx[n], cy = s_cy[n], wc = s_wc[n], hc = s_hc[n];
        float mind = 3.0e38f;
        int   mini = 0x7fffffff;
        for (int p = tid; p < P; p += 1024) {
            float2 r = rp2[p];
            float dx = (cx - r.x) / wc;
            float dy = (cy - r.y) / hc;
            float d = dx * dx + dy * dy;
            float de = (s_n[p] < n) ? SUPPRESS_V : d;
            if (de < mind) { mind = de; mini = p; }
        }
        for (int off = 16; off; off >>= 1) {
            float od = __shfl_down_sync(0xffffffffu, mind, off);
            int   oi = __shfl_down_sync(0xffffffffu, mini, off);
            if (od < mind || (od == mind && oi < mini)) { mind = od; mini = oi; }
        }
        if (lane == 0) { s_rd[warp] = mind; s_ri[warp] = mini; }
        __syncthreads();
        if (warp == 0) {
            mind = s_rd[lane]; mini = s_ri[lane];
            for (int off = 16; off; off >>= 1) {
                float od = __shfl_down_sync(0xffffffffu, mind, off);
                int   oi = __shfl_down_sync(0xffffffffu, mini, off);
                if (od < mind || (od == mind && oi < mini)) { mind = od; mini = oi; }
            }
            if (lane == 0) { s_gd = mind; s_gi = mini; }
        }
        __syncthreads();
        int p = s_gi;
        if ((p % 1024) == tid) {        // unique owner thread updates state
            int old = s_n[p];
            if (old < N_GT) s_cnt[old] -= 1;   // steal bookkeeping
            s_n[p] = (unsigned char)n;
            float dcl = fminf(s_gd, INNER_TH); // clip(d, 0, 0.5)
            keys[p] = ((unsigned long long)(unsigned)n << 32) |
                      (unsigned long long)__float_as_uint(dcl);
        }
        __syncthreads();
    }
}

// ---------------------------------------------------------------------------
// Phase 3: resolve keys -> outputs, writing the FULL md rows (incl. zeros)
// with coalesced float4 stores. Replaces the memset.
// ---------------------------------------------------------------------------
__global__ void __launch_bounds__(256)
phase3_kernel(float* __restrict__ out_ml,
              float* __restrict__ out_md,
              float* __restrict__ out_mi,
              int T, int P)
{
    int bt = blockIdx.y;
    int b = bt / T, t = bt % T;
    int p0 = blockIdx.x * 256;
    int tid = threadIdx.x;

    __shared__ int   sh_lab[N_GT];
    __shared__ float sh_gid[N_GT];
    __shared__ float s_sc[256];
    __shared__ int   s_col[256];

    if (tid < N_GT) {
        sh_lab[tid] = g_lab[b][tid];
        sh_gid[tid] = (float)g_id[b][tid][t];
    }
    s_col[tid] = -1;
    s_sc[tid]  = 0.0f;
    __syncthreads();

    int p = p0 + tid;
    if (p < P) {
        unsigned long long k = g_key[(size_t)bt * P + p];
        unsigned n = (unsigned)(k >> 32);
        float mlv = -1.0f, miv = -1.0f;
        if (n < N_GT) {
            int lab = sh_lab[n];
            mlv = (float)lab;
            miv = sh_gid[n];
            s_col[tid] = lab;
            float d = __uint_as_float((unsigned)k);
            s_sc[tid] = 1.0f - 2.0f * d;
        }
        out_ml[(size_t)bt * P + p] = mlv;
        out_mi[(size_t)bt * P + p] = miv;
    }
    __syncthreads();

    int npts = min(256, P - p0);
    if (npts <= 0) return;
    int nslots = npts * (NUM_CLASSES / 4);     // 10 float4 slots per point
    float4* mdb = (float4*)(out_md + ((size_t)bt * P + p0) * NUM_CLASSES);
    for (int s = tid; s < nslots; s += 256) {
        int pt = s / (NUM_CLASSES / 4);
        int c0 = (s % (NUM_CLASSES / 4)) * 4;
        float4 v = make_float4(0.f, 0.f, 0.f, 0.f);
        int col = s_col[pt];
        if (col >= c0 && col < c0 + 4)
            ((float*)&v)[col - c0] = s_sc[pt];
        mdb[s] = v;
    }
}

// ---------------------------------------------------------------------------
// Launch
// ---------------------------------------------------------------------------
extern "C" void kernel_launch(void* const* d_in, const int* in_sizes, int n_in,
                              void* d_out, int out_size)
{
    const int*   labels = (const int*)  d_in[0];   // [B,N]
    const float* boxes  = (const float*)d_in[1];   // [B,N,T,4]
    const int*   ids    = (const int*)  d_in[2];   // [B,N,T]
    const float* ref    = (const float*)d_in[3];   // [P,2]

    int BN = in_sizes[0];
    int B  = BN / N_GT;
    int T  = in_sizes[2] / BN;
    int P  = in_sizes[3] / 2;
    int BT = B * T;

    int W = (int)(sqrt((double)P) + 0.5);
    if ((long long)W * W != (long long)P) W = 0;   // disable bbox fast path

    float* out    = (float*)d_out;
    size_t mlN    = (size_t)BT * P;
    float* out_ml = out;
    float* out_md = out + mlN;
    float* out_mi = out + mlN + mlN * NUM_CLASSES;

    int total = BT * P;
    init_kernel<<<(total + 1023) / 1024, 1024>>>(total);
    prep_kernel<<<1, 256>>>(labels, boxes, ids, B, T);
    phase1_kernel<<<BT * N_GT, 256>>>(ref, T, P, W);
    phase2_kernel<<<BT, 1024>>>(ref, T, P);
    phase3_kernel<<<dim3((P + 255) / 256, BT), 256>>>(out_ml, out_md, out_mi, T, P);
}

// round 11
// speedup vs baseline: 1.0055x; 1.0055x over previous
#include <cuda_runtime.h>
#include <math.h>

#define NUM_CLASSES 40
#define N_GT 20
#define MAX_B 8
#define MAX_T 16
#define MAX_BT (MAX_B * MAX_T)
#define MAX_P 25600
#define INNER_TH 0.5f
#define SUPPRESS_V 1e9f

// Sorted (by mean area, ascending, stable) per-instance data.
// g_box: cx, cy, wclip(=max(w,0.05)), hclip
__device__ float4 g_box[MAX_B][N_GT][MAX_T];
__device__ int    g_lab[MAX_B][N_GT];
__device__ int    g_id [MAX_B][N_GT][MAX_T];
__device__ int    g_valid[MAX_B][N_GT];
// Per-point claim key: (claimer_n << 32) | f32bits(d).  ~0 = unclaimed.
__device__ unsigned long long g_key[MAX_BT * MAX_P];

// ---------------------------------------------------------------------------
// Init claim keys
// ---------------------------------------------------------------------------
__global__ void init_kernel(int total)
{
    int i = blockIdx.x * blockDim.x + threadIdx.x;
    if (i < total) g_key[i] = ~0ull;
}

// ---------------------------------------------------------------------------
// Prep: area -> stable argsort per batch -> gather sorted params
// ---------------------------------------------------------------------------
__global__ void prep_kernel(const int* __restrict__ labels,
                            const float* __restrict__ boxes,
                            const int* __restrict__ ids,
                            int B, int T)
{
    __shared__ float s_area[MAX_B][N_GT];
    __shared__ int   s_order[MAX_B][N_GT];
    int tid = threadIdx.x;
    int total = B * N_GT;

    if (tid < total) {
        int b = tid / N_GT, n = tid % N_GT;
        float sum = 0.0f;
        for (int t = 0; t < T; t++) {
            const float* bx = boxes + (((size_t)(b * N_GT + n) * T + t) * 4);
            float w = bx[2] - bx[0];
            float h = bx[3] - bx[1];
            sum += w * h;
        }
        s_area[b][n] = sum / (float)T;
    }
    __syncthreads();

    if (tid < B) {
        int b = tid;
        int ord[N_GT];
        for (int i = 0; i < N_GT; i++) ord[i] = i;
        for (int i = 1; i < N_GT; i++) {          // stable insertion sort
            int key = ord[i];
            float ka = s_area[b][key];
            int j = i - 1;
            while (j >= 0 && s_area[b][ord[j]] > ka) { ord[j + 1] = ord[j]; j--; }
            ord[j + 1] = key;
        }
        for (int i = 0; i < N_GT; i++) s_order[b][i] = ord[i];
    }
    __syncthreads();

    if (tid < total) {
        int b = tid / N_GT, n = tid % N_GT;
        int src = s_order[b][n];
        int lab = labels[b * N_GT + src];
        g_lab[b][n] = lab;
        int anyv = 0;
        for (int t = 0; t < T; t++) {
            const float* bx = boxes + (((size_t)(b * N_GT + src) * T + t) * 4);
            float x1 = bx[0], y1 = bx[1], x2 = bx[2], y2 = bx[3];
            float w = x2 - x1, h = y2 - y1;
            anyv |= (w > 0.0f && h > 0.0f) ? 1 : 0;
            float4 v;
            v.x = (x1 + x2) * 0.5f;
            v.y = (y1 + y2) * 0.5f;
            v.z = fmaxf(w, 0.05f);
            v.w = fmaxf(h, 0.05f);
            g_box[b][n][t] = v;
            g_id[b][n][t] = ids[(size_t)(b * N_GT + src) * T + t];
        }
        g_valid[b][n] = (anyv && lab >= 0) ? 1 : 0;
    }
}

// ---------------------------------------------------------------------------
// Phase 1: one block per (b,t,n). atomicMin packed (n, d) for every point
// inside the instance's d<0.5 ellipse (bbox-culled). Fully parallel.
// ---------------------------------------------------------------------------
__global__ void __launch_bounds__(256)
phase1_kernel(const float* __restrict__ ref, int T, int P, int W)
{
    int inst = blockIdx.x;                 // bt * N_GT + n
    int bt = inst / N_GT, n = inst % N_GT;
    int b = bt / T, t = bt % T;

    if (!g_valid[b][n]) return;
    int gid = g_id[b][n][t];
    if (gid == -1) return;

    float4 v = g_box[b][n][t];
    float cx = v.x, cy = v.y, wc = v.z, hc = v.w;
    float iw = 1.0f / wc, ih = 1.0f / hc;

    int ix0 = 0, iy0 = 0, bw = 0, cnt = P;
    if (W > 0) {
        int H = P / W;
        float Wf = (float)W, Hf = (float)H;
        float rx = wc * 0.7072f;
        float ry = hc * 0.7072f;
        ix0 = max(0,     (int)floorf((cx - rx) * Wf - 0.5f) - 2);
        int ix1 = min(W - 1, (int)ceilf((cx + rx) * Wf - 0.5f) + 2);
        iy0 = max(0,     (int)floorf((cy - ry) * Hf - 0.5f) - 2);
        int iy1 = min(H - 1, (int)ceilf((cy + ry) * Hf - 0.5f) + 2);
        bw = ix1 - ix0 + 1;
        cnt = (ix1 >= ix0 && iy1 >= iy0) ? bw * (iy1 - iy0 + 1) : 0;
    }

    const float2* rp2 = (const float2*)ref;
    unsigned long long base = (unsigned long long)(unsigned)n << 32;
    unsigned long long* keys = g_key + (size_t)bt * P;

    for (int idx = threadIdx.x; idx < cnt; idx += 256) {
        int p = (W > 0) ? ((iy0 + idx / bw) * W + (ix0 + idx % bw)) : idx;
        float2 r = rp2[p];
        float dx = (cx - r.x) * iw;
        float dy = (cy - r.y) * ih;
        float d = dx * dx + dy * dy;
        if (fabsf(d - INNER_TH) < 1e-5f) {
            // boundary band: redo with exact division (reference semantics)
            float ex = (cx - r.x) / wc;
            float ey = (cy - r.y) / hc;
            d = ex * ex + ey * ey;
        }
        if (d < INNER_TH)
            atomicMin(&keys[p], base | (unsigned long long)__float_as_uint(d));
    }
}

// ---------------------------------------------------------------------------
// Phase 2: one block per (b,t). Resolve rare fallback claims exactly.
// ---------------------------------------------------------------------------
__global__ void __launch_bounds__(1024)
phase2_kernel(const float* __restrict__ ref, int T, int P)
{
    int bt = blockIdx.x;
    int b = bt / T, t = bt % T;
    int tid = threadIdx.x;
    int lane = tid & 31, warp = tid >> 5;

    __shared__ unsigned char s_n[MAX_P];     // current claimer per point (255 = none)
    __shared__ int   s_cnt[N_GT];
    __shared__ int   s_act[N_GT];
    __shared__ float s_cx[N_GT], s_cy[N_GT], s_wc[N_GT], s_hc[N_GT];
    __shared__ float s_rd[32];
    __shared__ int   s_ri[32];
    __shared__ float s_gd;
    __shared__ int   s_gi;

    if (tid < N_GT) {
        float4 v = g_box[b][tid][t];
        s_cx[tid] = v.x; s_cy[tid] = v.y; s_wc[tid] = v.z; s_hc[tid] = v.w;
        int id = g_id[b][tid][t];
        s_act[tid] = (g_valid[b][tid] && id != -1) ? 1 : 0;
        s_cnt[tid] = 0;
    }
    __syncthreads();

    unsigned long long* keys = g_key + (size_t)bt * P;
    for (int p = tid; p < P; p += 1024) {
        unsigned long long k = keys[p];
        unsigned n = (unsigned)(k >> 32);
        unsigned char nn = (n < N_GT) ? (unsigned char)n : (unsigned char)255;
        s_n[p] = nn;
        if (nn < N_GT) atomicAdd(&s_cnt[nn], 1);
    }
    __syncthreads();

    const float2* rp2 = (const float2*)ref;

    for (int n = 0; n < N_GT; n++) {
        bool fb = s_act[n] && (s_cnt[n] == 0);   // uniform across block
        if (!fb) continue;

        float cx = s_cx[n], cy = s_cy[n], wc = s_wc[n], hc = s_hc[n];
        float mind = 3.0e38f;
        int   mini = 0x7fffffff;
        for (int p = tid; p < P; p += 1024) {
            float2 r = rp2[p];
            float dx = (cx - r.x) / wc;
            float dy = (cy - r.y) / hc;
            float d = dx * dx + dy * dy;
            float de = (s_n[p] < n) ? SUPPRESS_V : d;
            if (de < mind) { mind = de; mini = p; }
        }
        for (int off = 16; off; off >>= 1) {
            float od = __shfl_down_sync(0xffffffffu, mind, off);
            int   oi = __shfl_down_sync(0xffffffffu, mini, off);
            if (od < mind || (od == mind && oi < mini)) { mind = od; mini = oi; }
        }
        if (lane == 0) { s_rd[warp] = mind; s_ri[warp] = mini; }
        __syncthreads();
        if (warp == 0) {
            mind = s_rd[lane]; mini = s_ri[lane];
            for (int off = 16; off; off >>= 1) {
                float od = __shfl_down_sync(0xffffffffu, mind, off);
                int   oi = __shfl_down_sync(0xffffffffu, mini, off);
                if (od < mind || (od == mind && oi < mini)) { mind = od; mini = oi; }
            }
            if (lane == 0) { s_gd = mind; s_gi = mini; }
        }
        __syncthreads();
        int p = s_gi;
        if ((p % 1024) == tid) {        // unique owner thread updates state
            int old = s_n[p];
            if (old < N_GT) s_cnt[old] -= 1;   // steal bookkeeping
            s_n[p] = (unsigned char)n;
            float dcl = fminf(s_gd, INNER_TH); // clip(d, 0, 0.5)
            keys[p] = ((unsigned long long)(unsigned)n << 32) |
                      (unsigned long long)__float_as_uint(dcl);
        }
        __syncthreads();
    }
}

// ---------------------------------------------------------------------------
// Phase 3: resolve keys -> outputs, writing the FULL md rows (incl. zeros)
// with coalesced float4 stores. Replaces the memset.
// ---------------------------------------------------------------------------
__global__ void __launch_bounds__(256)
phase3_kernel(float* __restrict__ out_ml,
              float* __restrict__ out_md,
              float* __restrict__ out_mi,
              int T, int P)
{
    int bt = blockIdx.y;
    int b = bt / T, t = bt % T;
    int p0 = blockIdx.x * 256;
    int tid = threadIdx.x;

    __shared__ int   sh_lab[N_GT];
    __shared__ float sh_gid[N_GT];
    __shared__ float s_sc[256];
    __shared__ int   s_col[256];

    if (tid < N_GT) {
        sh_lab[tid] = g_lab[b][tid];
        sh_gid[tid] = (float)g_id[b][tid][t];
    }
    s_col[tid] = -1;
    s_sc[tid]  = 0.0f;
    __syncthreads();

    int p = p0 + tid;
    if (p < P) {
        unsigned long long k = g_key[(size_t)bt * P + p];
        unsigned n = (unsigned)(k >> 32);
        float mlv = -1.0f, miv = -1.0f;
        if (n < N_GT) {
            int lab = sh_lab[n];
            mlv = (float)lab;
            miv = sh_gid[n];
            s_col[tid] = lab;
            float d = __uint_as_float((unsigned)k);
            s_sc[tid] = 1.0f - 2.0f * d;
        }
        out_ml[(size_t)bt * P + p] = mlv;
        out_mi[(size_t)bt * P + p] = miv;
    }
    __syncthreads();

    int npts = min(256, P - p0);
    if (npts <= 0) return;
    int nslots = npts * (NUM_CLASSES / 4);     // 10 float4 slots per point
    float4* mdb = (float4*)(out_md + ((size_t)bt * P + p0) * NUM_CLASSES);
    for (int s = tid; s < nslots; s += 256) {
        int pt = s / (NUM_CLASSES / 4);
        int c0 = (s % (NUM_CLASSES / 4)) * 4;
        float4 v = make_float4(0.f, 0.f, 0.f, 0.f);
        int col = s_col[pt];
        if (col >= c0 && col < c0 + 4)
            ((float*)&v)[col - c0] = s_sc[pt];
        mdb[s] = v;
    }
}

// ---------------------------------------------------------------------------
// Launch
// ---------------------------------------------------------------------------
extern "C" void kernel_launch(void* const* d_in, const int* in_sizes, int n_in,
                              void* d_out, int out_size)
{
    const int*   labels = (const int*)  d_in[0];   // [B,N]
    const float* boxes  = (const float*)d_in[1];   // [B,N,T,4]
    const int*   ids    = (const int*)  d_in[2];   // [B,N,T]
    const float* ref    = (const float*)d_in[3];   // [P,2]

    int BN = in_sizes[0];
    int B  = BN / N_GT;
    int T  = in_sizes[2] / BN;
    int P  = in_sizes[3] / 2;
    int BT = B * T;

    int W = (int)(sqrt((double)P) + 0.5);
    if ((long long)W * W != (long long)P) W = 0;   // disable bbox fast path

    float* out    = (float*)d_out;
    size_t mlN    = (size_t)BT * P;
    float* out_ml = out;
    float* out_md = out + mlN;
    float* out_mi = out + mlN + mlN * NUM_CLASSES;

    int total = BT * P;
    init_kernel<<<(total + 1023) / 1024, 1024>>>(total);
    prep_kernel<<<1, 256>>>(labels, boxes, ids, B, T);
    phase1_kernel<<<BT * N_GT, 256>>>(ref, T, P, W);
    phase2_kernel<<<BT, 1024>>>(ref, T, P);
    phase3_kernel<<<dim3((P + 255) / 256, BT), 256>>>(out_ml, out_md, out_mi, T, P);
}

// round 12
// speedup vs baseline: 1.0194x; 1.0138x over previous
#include <cuda_runtime.h>
#include <math.h>

#define NUM_CLASSES 40
#define N_GT 20
#define MAX_B 8
#define MAX_T 16
#define MAX_BT (MAX_B * MAX_T)
#define MAX_P 25600
#define INNER_TH 0.5f
#define SUPPRESS_V 1e9f

// Sorted (by mean area, ascending, stable) per-instance data.
// g_box: cx, cy, wclip(=max(w,0.05)), hclip
__device__ float4 g_box[MAX_B][N_GT][MAX_T];
__device__ int    g_lab[MAX_B][N_GT];
__device__ int    g_id [MAX_B][N_GT][MAX_T];
__device__ int    g_valid[MAX_B][N_GT];
// Per-point claim key: (claimer_n << 32) | f32bits(d).  ~0 = unclaimed.
__device__ unsigned long long g_key[MAX_BT * MAX_P];
// Per-(bt,n) final inner-claim counts.
__device__ int g_cnt[MAX_BT * N_GT];

// ---------------------------------------------------------------------------
// Fused init (keys + counters) and prep (area sort + gather) — block 0 preps.
// ---------------------------------------------------------------------------
__global__ void __launch_bounds__(1024)
init_prep_kernel(const int* __restrict__ labels,
                 const float* __restrict__ boxes,
                 const int* __restrict__ ids,
                 int B, int T, int total)
{
    int i = blockIdx.x * blockDim.x + threadIdx.x;
    if (i < total) g_key[i] = ~0ull;
    if (i < MAX_BT * N_GT) g_cnt[i] = 0;

    if (blockIdx.x != 0) return;

    // ----- prep (block 0 only; all 1024 threads participate in barriers) ---
    __shared__ float s_area[MAX_B][N_GT];
    __shared__ int   s_order[MAX_B][N_GT];
    int tid = threadIdx.x;
    int tot = B * N_GT;

    if (tid < tot) {
        int b = tid / N_GT, n = tid % N_GT;
        float sum = 0.0f;
        for (int t = 0; t < T; t++) {
            const float* bx = boxes + (((size_t)(b * N_GT + n) * T + t) * 4);
            float w = bx[2] - bx[0];
            float h = bx[3] - bx[1];
            sum += w * h;
        }
        s_area[b][n] = sum / (float)T;
    }
    __syncthreads();

    if (tid < B) {
        int b = tid;
        int ord[N_GT];
        for (int i2 = 0; i2 < N_GT; i2++) ord[i2] = i2;
        for (int i2 = 1; i2 < N_GT; i2++) {       // stable insertion sort
            int key = ord[i2];
            float ka = s_area[b][key];
            int j = i2 - 1;
            while (j >= 0 && s_area[b][ord[j]] > ka) { ord[j + 1] = ord[j]; j--; }
            ord[j + 1] = key;
        }
        for (int i2 = 0; i2 < N_GT; i2++) s_order[b][i2] = ord[i2];
    }
    __syncthreads();

    if (tid < tot) {
        int b = tid / N_GT, n = tid % N_GT;
        int src = s_order[b][n];
        int lab = labels[b * N_GT + src];
        g_lab[b][n] = lab;
        int anyv = 0;
        for (int t = 0; t < T; t++) {
            const float* bx = boxes + (((size_t)(b * N_GT + src) * T + t) * 4);
            float x1 = bx[0], y1 = bx[1], x2 = bx[2], y2 = bx[3];
            float w = x2 - x1, h = y2 - y1;
            anyv |= (w > 0.0f && h > 0.0f) ? 1 : 0;
            float4 v;
            v.x = (x1 + x2) * 0.5f;
            v.y = (y1 + y2) * 0.5f;
            v.z = fmaxf(w, 0.05f);
            v.w = fmaxf(h, 0.05f);
            g_box[b][n][t] = v;
            g_id[b][n][t] = ids[(size_t)(b * N_GT + src) * T + t];
        }
        g_valid[b][n] = (anyv && lab >= 0) ? 1 : 0;
    }
}

// ---------------------------------------------------------------------------
// Phase 1: one block per (b,t,n). atomicMin packed (n, d) for every point
// inside the instance's d<0.5 ellipse (bbox-culled). Fully parallel.
// ---------------------------------------------------------------------------
__global__ void __launch_bounds__(256)
phase1_kernel(const float* __restrict__ ref, int T, int P, int W)
{
    int inst = blockIdx.x;                 // bt * N_GT + n
    int bt = inst / N_GT, n = inst % N_GT;
    int b = bt / T, t = bt % T;

    if (!g_valid[b][n]) return;
    int gid = g_id[b][n][t];
    if (gid == -1) return;

    float4 v = g_box[b][n][t];
    float cx = v.x, cy = v.y, wc = v.z, hc = v.w;
    float iw = 1.0f / wc, ih = 1.0f / hc;

    int ix0 = 0, iy0 = 0, bw = 0, cnt = P;
    if (W > 0) {
        int H = P / W;
        float Wf = (float)W, Hf = (float)H;
        float rx = wc * 0.7072f;
        float ry = hc * 0.7072f;
        ix0 = max(0,     (int)floorf((cx - rx) * Wf - 0.5f) - 2);
        int ix1 = min(W - 1, (int)ceilf((cx + rx) * Wf - 0.5f) + 2);
        iy0 = max(0,     (int)floorf((cy - ry) * Hf - 0.5f) - 2);
        int iy1 = min(H - 1, (int)ceilf((cy + ry) * Hf - 0.5f) + 2);
        bw = ix1 - ix0 + 1;
        cnt = (ix1 >= ix0 && iy1 >= iy0) ? bw * (iy1 - iy0 + 1) : 0;
    }

    const float2* rp2 = (const float2*)ref;
    unsigned long long base = (unsigned long long)(unsigned)n << 32;
    unsigned long long* keys = g_key + (size_t)bt * P;

    for (int idx = threadIdx.x; idx < cnt; idx += 256) {
        int p = (W > 0) ? ((iy0 + idx / bw) * W + (ix0 + idx % bw)) : idx;
        float2 r = rp2[p];
        float dx = (cx - r.x) * iw;
        float dy = (cy - r.y) * ih;
        float d = dx * dx + dy * dy;
        if (fabsf(d - INNER_TH) < 1e-5f) {
            // boundary band: redo with exact division (reference semantics)
            float ex = (cx - r.x) / wc;
            float ey = (cy - r.y) / hc;
            d = ex * ex + ey * ey;
        }
        if (d < INNER_TH)
            atomicMin(&keys[p], base | (unsigned long long)__float_as_uint(d));
    }
}

// ---------------------------------------------------------------------------
// Phase 2a: full-chip histogram of final claimers into g_cnt[bt][n].
// One block per 256-point chunk of one bt.
// ---------------------------------------------------------------------------
__global__ void __launch_bounds__(256)
count_kernel(int P)
{
    __shared__ int h[N_GT];
    int tid = threadIdx.x;
    if (tid < N_GT) h[tid] = 0;
    __syncthreads();

    int bt = blockIdx.y;
    int p = blockIdx.x * 256 + tid;
    if (p < P) {
        unsigned long long k = g_key[(size_t)bt * P + p];
        unsigned n = (unsigned)(k >> 32);
        if (n < N_GT) atomicAdd(&h[n], 1);
    }
    __syncthreads();
    if (tid < N_GT && h[tid] > 0)
        atomicAdd(&g_cnt[bt * N_GT + tid], h[tid]);
}

// ---------------------------------------------------------------------------
// Phase 2b: one block per (b,t). Early-exit unless some active instance has
// zero inner claims; only then run the exact sequential fallback/steal logic.
// ---------------------------------------------------------------------------
__global__ void __launch_bounds__(1024)
fallback_kernel(const float* __restrict__ ref, int T, int P)
{
    int bt = blockIdx.x;
    int b = bt / T, t = bt % T;
    int tid = threadIdx.x;
    int lane = tid & 31, warp = tid >> 5;

    __shared__ int   s_cnt[N_GT];
    __shared__ int   s_act[N_GT];
    __shared__ int   s_need;
    __shared__ float s_cx[N_GT], s_cy[N_GT], s_wc[N_GT], s_hc[N_GT];

    if (tid == 0) s_need = 0;
    if (tid < N_GT) {
        int id = g_id[b][tid][t];
        int act = (g_valid[b][tid] && id != -1) ? 1 : 0;
        int c = g_cnt[bt * N_GT + tid];
        s_act[tid] = act;
        s_cnt[tid] = c;
        float4 v = g_box[b][tid][t];
        s_cx[tid] = v.x; s_cy[tid] = v.y; s_wc[tid] = v.z; s_hc[tid] = v.w;
    }
    __syncthreads();
    if (tid == 0) {
        int need = 0;
        for (int n = 0; n < N_GT; n++)
            if (s_act[n] && s_cnt[n] == 0) need = 1;
        s_need = need;
    }
    __syncthreads();
    if (!s_need) return;                     // common case: nothing to do

    // ----- rare path: load claimers and run exact sequential steals --------
    __shared__ unsigned char s_n[MAX_P];
    __shared__ float s_rd[32];
    __shared__ int   s_ri[32];
    __shared__ float s_gd;
    __shared__ int   s_gi;

    unsigned long long* keys = g_key + (size_t)bt * P;
    for (int p = tid; p < P; p += 1024) {
        unsigned long long k = keys[p];
        unsigned n = (unsigned)(k >> 32);
        s_n[p] = (n < N_GT) ? (unsigned char)n : (unsigned char)255;
    }
    __syncthreads();

    const float2* rp2 = (const float2*)ref;

    for (int n = 0; n < N_GT; n++) {
        bool fb = s_act[n] && (s_cnt[n] == 0);   // uniform across block
        if (!fb) continue;

        float cx = s_cx[n], cy = s_cy[n], wc = s_wc[n], hc = s_hc[n];
        float mind = 3.0e38f;
        int   mini = 0x7fffffff;
        for (int p = tid; p < P; p += 1024) {
            float2 r = rp2[p];
            float dx = (cx - r.x) / wc;
            float dy = (cy - r.y) / hc;
            float d = dx * dx + dy * dy;
            float de = (s_n[p] < n) ? SUPPRESS_V : d;
            if (de < mind) { mind = de; mini = p; }
        }
        for (int off = 16; off; off >>= 1) {
            float od = __shfl_down_sync(0xffffffffu, mind, off);
            int   oi = __shfl_down_sync(0xffffffffu, mini, off);
            if (od < mind || (od == mind && oi < mini)) { mind = od; mini = oi; }
        }
        if (lane == 0) { s_rd[warp] = mind; s_ri[warp] = mini; }
        __syncthreads();
        if (warp == 0) {
            mind = s_rd[lane]; mini = s_ri[lane];
            for (int off = 16; off; off >>= 1) {
                float od = __shfl_down_sync(0xffffffffu, mind, off);
                int   oi = __shfl_down_sync(0xffffffffu, mini, off);
                if (od < mind || (od == mind && oi < mini)) { mind = od; mini = oi; }
            }
            if (lane == 0) { s_gd = mind; s_gi = mini; }
        }
        __syncthreads();
        int p = s_gi;
        if ((p % 1024) == tid) {        // unique owner thread updates state
            int old = s_n[p];
            if (old < N_GT) s_cnt[old] -= 1;   // steal bookkeeping (cascades)
            s_cnt[n] += 1;
            s_n[p] = (unsigned char)n;
            float dcl = fminf(s_gd, INNER_TH); // clip(d, 0, 0.5)
            keys[p] = ((unsigned long long)(unsigned)n << 32) |
                      (unsigned long long)__float_as_uint(dcl);
        }
        __syncthreads();
    }
}

// ---------------------------------------------------------------------------
// Phase 3: resolve keys -> outputs, writing the FULL md rows (incl. zeros)
// with coalesced float4 stores.
// ---------------------------------------------------------------------------
__global__ void __launch_bounds__(256)
phase3_kernel(float* __restrict__ out_ml,
              float* __restrict__ out_md,
              float* __restrict__ out_mi,
              int T, int P)
{
    int bt = blockIdx.y;
    int b = bt / T, t = bt % T;
    int p0 = blockIdx.x * 256;
    int tid = threadIdx.x;

    __shared__ int   sh_lab[N_GT];
    __shared__ float sh_gid[N_GT];
    __shared__ float s_sc[256];
    __shared__ int   s_col[256];

    if (tid < N_GT) {
        sh_lab[tid] = g_lab[b][tid];
        sh_gid[tid] = (float)g_id[b][tid][t];
    }
    s_col[tid] = -1;
    s_sc[tid]  = 0.0f;
    __syncthreads();

    int p = p0 + tid;
    if (p < P) {
        unsigned long long k = g_key[(size_t)bt * P + p];
        unsigned n = (unsigned)(k >> 32);
        float mlv = -1.0f, miv = -1.0f;
        if (n < N_GT) {
            int lab = sh_lab[n];
            mlv = (float)lab;
            miv = sh_gid[n];
            s_col[tid] = lab;
            float d = __uint_as_float((unsigned)k);
            s_sc[tid] = 1.0f - 2.0f * d;
        }
        out_ml[(size_t)bt * P + p] = mlv;
        out_mi[(size_t)bt * P + p] = miv;
    }
    __syncthreads();

    int npts = min(256, P - p0);
    if (npts <= 0) return;
    int nslots = npts * (NUM_CLASSES / 4);     // 10 float4 slots per point
    float4* mdb = (float4*)(out_md + ((size_t)bt * P + p0) * NUM_CLASSES);
    for (int s = tid; s < nslots; s += 256) {
        int pt = s / (NUM_CLASSES / 4);
        int c0 = (s % (NUM_CLASSES / 4)) * 4;
        float4 v = make_float4(0.f, 0.f, 0.f, 0.f);
        int col = s_col[pt];
        if (col >= c0 && col < c0 + 4)
            ((float*)&v)[col - c0] = s_sc[pt];
        mdb[s] = v;
    }
}

// ---------------------------------------------------------------------------
// Launch
// ---------------------------------------------------------------------------
extern "C" void kernel_launch(void* const* d_in, const int* in_sizes, int n_in,
                              void* d_out, int out_size)
{
    const int*   labels = (const int*)  d_in[0];   // [B,N]
    const float* boxes  = (const float*)d_in[1];   // [B,N,T,4]
    const int*   ids    = (const int*)  d_in[2];   // [B,N,T]
    const float* ref    = (const float*)d_in[3];   // [P,2]

    int BN = in_sizes[0];
    int B  = BN / N_GT;
    int T  = in_sizes[2] / BN;
    int P  = in_sizes[3] / 2;
    int BT = B * T;

    int W = (int)(sqrt((double)P) + 0.5);
    if ((long long)W * W != (long long)P) W = 0;   // disable bbox fast path

    float* out    = (float*)d_out;
    size_t mlN    = (size_t)BT * P;
    float* out_ml = out;
    float* out_md = out + mlN;
    float* out_mi = out + mlN + mlN * NUM_CLASSES;

    int total = BT * P;
    int pchunks = (P + 255) / 256;

    init_prep_kernel<<<(total + 1023) / 1024, 1024>>>(labels, boxes, ids, B, T, total);
    phase1_kernel<<<BT * N_GT, 256>>>(ref, T, P, W);
    count_kernel<<<dim3(pchunks, BT), 256>>>(P);
    fallback_kernel<<<BT, 1024>>>(ref, T, P);
    phase3_kernel<<<dim3(pchunks, BT), 256>>>(out_ml, out_md, out_mi, T, P);
}

// round 16
// speedup vs baseline: 1.1478x; 1.1260x over previous
#include <cuda_runtime.h>
#include <math.h>

#define NUM_CLASSES 40
#define N_GT 20
#define MAX_B 8
#define MAX_T 16
#define MAX_BT (MAX_B * MAX_T)
#define MAX_P 25600
#define INNER_TH 0.5f
#define SUPPRESS_V 1e9f

// Sorted (by mean area, ascending, stable) per-instance data.
// g_box: cx, cy, wclip(=max(w,0.05)), hclip
__device__ float4 g_box[MAX_B][N_GT][MAX_T];
__device__ int    g_lab[MAX_B][N_GT];
__device__ int    g_id [MAX_B][N_GT][MAX_T];
__device__ int    g_valid[MAX_B][N_GT];
// Per-point claim key: (claimer_n << 32) | f32bits(d).  ~0 = unclaimed.
__device__ unsigned long long g_key[MAX_BT * MAX_P];
// Per-(bt,n) final inner-claim counts.
__device__ int g_cnt[MAX_BT * N_GT];

// ---------------------------------------------------------------------------
// Fused init (keys + counters) and prep (area sort + gather) — block 0 preps.
// ---------------------------------------------------------------------------
__global__ void __launch_bounds__(1024)
init_prep_kernel(const int* __restrict__ labels,
                 const float* __restrict__ boxes,
                 const int* __restrict__ ids,
                 int B, int T, int total)
{
    int i = blockIdx.x * blockDim.x + threadIdx.x;
    if (i < total) g_key[i] = ~0ull;
    if (i < MAX_BT * N_GT) g_cnt[i] = 0;

    if (blockIdx.x != 0) return;

    __shared__ float s_area[MAX_B][N_GT];
    __shared__ int   s_order[MAX_B][N_GT];
    int tid = threadIdx.x;
    int tot = B * N_GT;

    if (tid < tot) {
        int b = tid / N_GT, n = tid % N_GT;
        float sum = 0.0f;
        for (int t = 0; t < T; t++) {
            const float* bx = boxes + (((size_t)(b * N_GT + n) * T + t) * 4);
            float w = bx[2] - bx[0];
            float h = bx[3] - bx[1];
            sum += w * h;
        }
        s_area[b][n] = sum / (float)T;
    }
    __syncthreads();

    if (tid < B) {
        int b = tid;
        int ord[N_GT];
        for (int i2 = 0; i2 < N_GT; i2++) ord[i2] = i2;
        for (int i2 = 1; i2 < N_GT; i2++) {       // stable insertion sort
            int key = ord[i2];
            float ka = s_area[b][key];
            int j = i2 - 1;
            while (j >= 0 && s_area[b][ord[j]] > ka) { ord[j + 1] = ord[j]; j--; }
            ord[j + 1] = key;
        }
        for (int i2 = 0; i2 < N_GT; i2++) s_order[b][i2] = ord[i2];
    }
    __syncthreads();

    if (tid < tot) {
        int b = tid / N_GT, n = tid % N_GT;
        int src = s_order[b][n];
        int lab = labels[b * N_GT + src];
        g_lab[b][n] = lab;
        int anyv = 0;
        for (int t = 0; t < T; t++) {
            const float* bx = boxes + (((size_t)(b * N_GT + src) * T + t) * 4);
            float x1 = bx[0], y1 = bx[1], x2 = bx[2], y2 = bx[3];
            float w = x2 - x1, h = y2 - y1;
            anyv |= (w > 0.0f && h > 0.0f) ? 1 : 0;
            float4 v;
            v.x = (x1 + x2) * 0.5f;
            v.y = (y1 + y2) * 0.5f;
            v.z = fmaxf(w, 0.05f);
            v.w = fmaxf(h, 0.05f);
            g_box[b][n][t] = v;
            g_id[b][n][t] = ids[(size_t)(b * N_GT + src) * T + t];
        }
        g_valid[b][n] = (anyv && lab >= 0) ? 1 : 0;
    }
}

// ---------------------------------------------------------------------------
// Phase 1: one block per (b,t,n). atomicMin packed (n, d) for every point
// inside the instance's d<0.5 ellipse (bbox-culled). Fully parallel.
// ---------------------------------------------------------------------------
__global__ void __launch_bounds__(256)
phase1_kernel(const float* __restrict__ ref, int T, int P, int W)
{
    int inst = blockIdx.x;                 // bt * N_GT + n
    int bt = inst / N_GT, n = inst % N_GT;
    int b = bt / T, t = bt % T;

    if (!g_valid[b][n]) return;
    int gid = g_id[b][n][t];
    if (gid == -1) return;

    float4 v = g_box[b][n][t];
    float cx = v.x, cy = v.y, wc = v.z, hc = v.w;
    float iw = 1.0f / wc, ih = 1.0f / hc;

    int ix0 = 0, iy0 = 0, bw = 0, cnt = P;
    if (W > 0) {
        int H = P / W;
        float Wf = (float)W, Hf = (float)H;
        float rx = wc * 0.7072f;
        float ry = hc * 0.7072f;
        ix0 = max(0,     (int)floorf((cx - rx) * Wf - 0.5f) - 2);
        int ix1 = min(W - 1, (int)ceilf((cx + rx) * Wf - 0.5f) + 2);
        iy0 = max(0,     (int)floorf((cy - ry) * Hf - 0.5f) - 2);
        int iy1 = min(H - 1, (int)ceilf((cy + ry) * Hf - 0.5f) + 2);
        bw = ix1 - ix0 + 1;
        cnt = (ix1 >= ix0 && iy1 >= iy0) ? bw * (iy1 - iy0 + 1) : 0;
    }

    const float2* rp2 = (const float2*)ref;
    unsigned long long base = (unsigned long long)(unsigned)n << 32;
    unsigned long long* keys = g_key + (size_t)bt * P;

    for (int idx = threadIdx.x; idx < cnt; idx += 256) {
        int p = (W > 0) ? ((iy0 + idx / bw) * W + (ix0 + idx % bw)) : idx;
        float2 r = rp2[p];
        float dx = (cx - r.x) * iw;
        float dy = (cy - r.y) * ih;
        float d = dx * dx + dy * dy;
        if (fabsf(d - INNER_TH) < 1e-5f) {
            // boundary band: redo with exact division (reference semantics)
            float ex = (cx - r.x) / wc;
            float ey = (cy - r.y) / hc;
            d = ex * ex + ey * ey;
        }
        if (d < INNER_TH)
            atomicMin(&keys[p], base | (unsigned long long)__float_as_uint(d));
    }
}

// ---------------------------------------------------------------------------
// Phase 2a: full-chip histogram of final claimers into g_cnt[bt][n].
// ---------------------------------------------------------------------------
__global__ void __launch_bounds__(256)
count_kernel(int P)
{
    __shared__ int h[N_GT];
    int tid = threadIdx.x;
    if (tid < N_GT) h[tid] = 0;
    __syncthreads();

    int bt = blockIdx.y;
    int p = blockIdx.x * 256 + tid;
    if (p < P) {
        unsigned long long k = g_key[(size_t)bt * P + p];
        unsigned n = (unsigned)(k >> 32);
        if (n < N_GT) atomicAdd(&h[n], 1);
    }
    __syncthreads();
    if (tid < N_GT && h[tid] > 0)
        atomicAdd(&g_cnt[bt * N_GT + tid], h[tid]);
}

// ---------------------------------------------------------------------------
// Phase 2b: one block per (b,t). Exact sequential fallback/steal logic with
// expanding-box argmin (any point outside box(D) has d > D) and
// reciprocal-multiply distance. Fallback scores are identically 0 in the
// reference (winner d >= 0.5, clip -> 0.5 -> score 0), so keys get d=0.5.
// ---------------------------------------------------------------------------
__global__ void __launch_bounds__(1024)
fallback_kernel(const float* __restrict__ ref, int T, int P, int W)
{
    int bt = blockIdx.x;
    int b = bt / T, t = bt % T;
    int tid = threadIdx.x;
    int lane = tid & 31, warp = tid >> 5;

    __shared__ int   s_cnt[N_GT];
    __shared__ int   s_act[N_GT];
    __shared__ int   s_need;
    __shared__ float s_cx[N_GT], s_cy[N_GT], s_wc[N_GT], s_hc[N_GT];

    if (tid == 0) s_need = 0;
    if (tid < N_GT) {
        int id = g_id[b][tid][t];
        s_act[tid] = (g_valid[b][tid] && id != -1) ? 1 : 0;
        s_cnt[tid] = g_cnt[bt * N_GT + tid];
        float4 v = g_box[b][tid][t];
        s_cx[tid] = v.x; s_cy[tid] = v.y; s_wc[tid] = v.z; s_hc[tid] = v.w;
    }
    __syncthreads();
    if (tid == 0) {
        int need = 0;
        for (int n = 0; n < N_GT; n++)
            if (s_act[n] && s_cnt[n] == 0) need = 1;
        s_need = need;
    }
    __syncthreads();
    if (!s_need) return;

    __shared__ unsigned char s_n[MAX_P];     // claimer per point (255 = none)
    __shared__ float s_rd[32];
    __shared__ int   s_ri[32];
    __shared__ float s_gd;
    __shared__ int   s_gi;

    unsigned long long* keys = g_key + (size_t)bt * P;
    for (int p = tid; p < P; p += 1024) {
        unsigned long long k = keys[p];
        unsigned n = (unsigned)(k >> 32);
        s_n[p] = (n < N_GT) ? (unsigned char)n : (unsigned char)255;
    }
    __syncthreads();

    const float2* rp2 = (const float2*)ref;
    int H = (W > 0) ? (P / W) : 0;
    float Wf = (float)W, Hf = (float)H;

    for (int n = 0; n < N_GT; n++) {
        bool fb = s_act[n] && (s_cnt[n] == 0);   // uniform across block
        if (!fb) continue;

        float cx = s_cx[n], cy = s_cy[n], wc = s_wc[n], hc = s_hc[n];
        float iw = 1.0f / wc, ih = 1.0f / hc;

        float D = 1.0f;
        for (;;) {
            // box covering all points with d <= D (points outside have d > D)
            int ix0 = 0, iy0 = 0, bw = W, cnt = P;
            bool full = true;
            if (W > 0) {
                float rx = wc * sqrtf(D), ry = hc * sqrtf(D);
                ix0 = max(0,     (int)floorf((cx - rx) * Wf - 0.5f) - 1);
                int ix1 = min(W - 1, (int)ceilf((cx + rx) * Wf - 0.5f) + 1);
                iy0 = max(0,     (int)floorf((cy - ry) * Hf - 0.5f) - 1);
                int iy1 = min(H - 1, (int)ceilf((cy + ry) * Hf - 0.5f) + 1);
                bw = ix1 - ix0 + 1;
                cnt = bw * (iy1 - iy0 + 1);
                full = (ix0 == 0 && iy0 == 0 && ix1 == W - 1 && iy1 == H - 1);
            }

            float mind = 3.0e38f;
            int   mini = 0x7fffffff;
            for (int idx = tid; idx < cnt; idx += 1024) {
                int p = (W > 0) ? ((iy0 + idx / bw) * W + (ix0 + idx % bw)) : idx;
                float2 r = rp2[p];
                float dx = (cx - r.x) * iw;
                float dy = (cy - r.y) * ih;
                float d = dx * dx + dy * dy;
                float de = (s_n[p] < n) ? SUPPRESS_V : d;
                if (de < mind) { mind = de; mini = p; }   // p ascending => first-min
            }
            for (int off = 16; off; off >>= 1) {
                float od = __shfl_down_sync(0xffffffffu, mind, off);
                int   oi = __shfl_down_sync(0xffffffffu, mini, off);
                if (od < mind || (od == mind && oi < mini)) { mind = od; mini = oi; }
            }
            if (lane == 0) { s_rd[warp] = mind; s_ri[warp] = mini; }
            __syncthreads();
            if (warp == 0) {
                mind = (lane * 32 < 1024) ? s_rd[lane] : 3.0e38f;
                mini = (lane * 32 < 1024) ? s_ri[lane] : 0x7fffffff;
                for (int off = 16; off; off >>= 1) {
                    float od = __shfl_down_sync(0xffffffffu, mind, off);
                    int   oi = __shfl_down_sync(0xffffffffu, mini, off);
                    if (od < mind || (od == mind && oi < mini)) { mind = od; mini = oi; }
                }
                if (lane == 0) { s_gd = mind; s_gi = mini; }
            }
            __syncthreads();
            if (full || s_gd <= D * 0.99999f) break;
            D *= 4.0f;
            __syncthreads();
        }

        int p = s_gi;
        if ((p % 1024) == tid) {        // unique owner thread updates state
            int old = s_n[p];
            if (old < N_GT) s_cnt[old] -= 1;   // steal bookkeeping (cascades)
            s_cnt[n] += 1;
            s_n[p] = (unsigned char)n;
            // fallback winner always has d >= 0.5 (or is suppressed):
            // clip(d,0,0.5) = 0.5 exactly -> score 0
            keys[p] = ((unsigned long long)(unsigned)n << 32) |
                      (unsigned long long)__float_as_uint(INNER_TH);
        }
        __syncthreads();
    }
}

// ---------------------------------------------------------------------------
// Phase 3: resolve keys -> outputs, writing the FULL md rows (incl. zeros)
// with coalesced float4 stores.
// ---------------------------------------------------------------------------
__global__ void __launch_bounds__(256)
phase3_kernel(float* __restrict__ out_ml,
              float* __restrict__ out_md,
              float* __restrict__ out_mi,
              int T, int P)
{
    int bt = blockIdx.y;
    int b = bt / T, t = bt % T;
    int p0 = blockIdx.x * 256;
    int tid = threadIdx.x;

    __shared__ int   sh_lab[N_GT];
    __shared__ float sh_gid[N_GT];
    __shared__ float s_sc[256];
    __shared__ int   s_col[256];

    if (tid < N_GT) {
        sh_lab[tid] = g_lab[b][tid];
        sh_gid[tid] = (float)g_id[b][tid][t];
    }
    s_col[tid] = -1;
    s_sc[tid]  = 0.0f;
    __syncthreads();

    int p = p0 + tid;
    if (p < P) {
        unsigned long long k = g_key[(size_t)bt * P + p];
        unsigned n = (unsigned)(k >> 32);
        float mlv = -1.0f, miv = -1.0f;
        if (n < N_GT) {
            int lab = sh_lab[n];
            mlv = (float)lab;
            miv = sh_gid[n];
            s_col[tid] = lab;
            float d = __uint_as_float((unsigned)k);
            s_sc[tid] = 1.0f - 2.0f * d;
        }
        out_ml[(size_t)bt * P + p] = mlv;
        out_mi[(size_t)bt * P + p] = miv;
    }
    __syncthreads();

    int npts = min(256, P - p0);
    if (npts <= 0) return;
    int nslots = npts * (NUM_CLASSES / 4);     // 10 float4 slots per point
    float4* mdb = (float4*)(out_md + ((size_t)bt * P + p0) * NUM_CLASSES);
    for (int s = tid; s < nslots; s += 256) {
        int pt = s / (NUM_CLASSES / 4);
        int c0 = (s % (NUM_CLASSES / 4)) * 4;
        float4 v = make_float4(0.f, 0.f, 0.f, 0.f);
        int col = s_col[pt];
        if (col >= c0 && col < c0 + 4)
            ((float*)&v)[col - c0] = s_sc[pt];
        mdb[s] = v;
    }
}

// ---------------------------------------------------------------------------
// Launch
// ---------------------------------------------------------------------------
extern "C" void kernel_launch(void* const* d_in, const int* in_sizes, int n_in,
                              void* d_out, int out_size)
{
    const int*   labels = (const int*)  d_in[0];   // [B,N]
    const float* boxes  = (const float*)d_in[1];   // [B,N,T,4]
    const int*   ids    = (const int*)  d_in[2];   // [B,N,T]
    const float* ref    = (const float*)d_in[3];   // [P,2]

    int BN = in_sizes[0];
    int B  = BN / N_GT;
    int T  = in_sizes[2] / BN;
    int P  = in_sizes[3] / 2;
    int BT = B * T;

    int W = (int)(sqrt((double)P) + 0.5);
    if ((long long)W * W != (long long)P) W = 0;   // disable bbox fast path

    float* out    = (float*)d_out;
    size_t mlN    = (size_t)BT * P;
    float* out_ml = out;
    float* out_md = out + mlN;
    float* out_mi = out + mlN + mlN * NUM_CLASSES;

    int total = BT * P;
    int pchunks = (P + 255) / 256;

    init_prep_kernel<<<(total + 1023) / 1024, 1024>>>(labels, boxes, ids, B, T, total);
    phase1_kernel<<<BT * N_GT, 256>>>(ref, T, P, W);
    count_kernel<<<dim3(pchunks, BT), 256>>>(P);
    fallback_kernel<<<BT, 1024>>>(ref, T, P, W);
    phase3_kernel<<<dim3(pchunks, BT), 256>>>(out_ml, out_md, out_mi, T, P);
}